// round 6
// baseline (speedup 1.0000x reference)
#include <cuda_runtime.h>
#include <cuda_bf16.h>

typedef unsigned long long u64;

#define NBH 1024   // B*H
#define TT  4
#define DK  128
#define DV  256
#define NTILE (NBH * 4)
#define GRID  592   // 148 SMs * 4 CTAs -> fully resident persistent grid

// ---- packed f32x2 helpers (Blackwell sm_103a) ----
__device__ __forceinline__ u64 pk2(float x, float y){
    u64 r; asm("mov.b64 %0, {%1,%2};" : "=l"(r) : "f"(x), "f"(y)); return r;
}
__device__ __forceinline__ u64 pk1(float x){ return pk2(x, x); }
__device__ __forceinline__ void up2(u64 a, float& x, float& y){
    asm("mov.b64 {%0,%1}, %2;" : "=f"(x), "=f"(y) : "l"(a));
}
__device__ __forceinline__ u64 fma2(u64 a, u64 b, u64 c){
    u64 d; asm("fma.rn.f32x2 %0, %1, %2, %3;" : "=l"(d) : "l"(a), "l"(b), "l"(c)); return d;
}
__device__ __forceinline__ u64 mul2(u64 a, u64 b){
    u64 d; asm("mul.rn.f32x2 %0, %1, %2;" : "=l"(d) : "l"(a), "l"(b)); return d;
}

// Persistent CTAs; each tile = one (b,h) x one quarter of Dv (64 cols).
//   cg = tid & 15 -> 4 consecutive cols; rg = tid >> 4 -> 8 consecutive rows.
// State slice 8x4 fp32 in registers. Decay factored out (state = c*S').
// kq fusion: out = c*(S'_old.q + (k.q)*d') -> ONE reduction (2 barriers)/step.
// q/k/v/g/beta read directly from global (L1/L2 resident, broadcast) -- no
// staging smem, no staging barrier. Reduction buffers parity double-buffered;
// every reuse is >=2 barriers after the last read (also across tiles).
__global__ __launch_bounds__(256, 4)
void gdn_step_kernel(const float* __restrict__ q, const float* __restrict__ k,
                     const float* __restrict__ v, const float* __restrict__ g,
                     const float* __restrict__ beta, const float* __restrict__ s0,
                     float* __restrict__ out, float* __restrict__ sout)
{
    const int tid = threadIdx.x;
    const int cg  = tid & 15;    // column group (4 cols)
    const int rg  = tid >> 4;    // row group (8 rows)
    const int k0  = rg * 8;

    __shared__ float4 redA[2][256];    // k-dot partials (4 cols)
    __shared__ float4 redB[2][256];    // q-dot partials (4 cols)
    __shared__ float  redC[2][256];    // k.q scalar partials
    __shared__ float4 sumsA[2][16];
    __shared__ float4 sumsB[2][16];
    __shared__ float  sumsC[2][16];

    for (int tile = blockIdx.x; tile < NTILE; tile += GRID){
        const int bh    = tile >> 2;
        const int vbase = (tile & 3) * 64;
        const int v0    = vbase + cg * 4;
        const size_t sbase = (size_t)bh * (DK * DV);

        // ---- front-batched state load: 8 x LDG.128 streaming, coalesced ----
        ulonglong2 S[8];
#pragma unroll
        for (int kk = 0; kk < 8; kk++){
            float4 f = __ldcs((const float4*)(s0 + sbase + (size_t)(k0 + kk) * DV + v0));
            S[kk].x = pk2(f.x, f.y);
            S[kk].y = pk2(f.z, f.w);
        }

        float c = 1.0f;   // cumulative decay; true state = c * S'
#pragma unroll
        for (int t = 0; t < TT; t++){
            const int buf = t & 1;
            c *= __expf(__ldg(g + bh * TT + t));

            // direct global k/q fetch for this thread's 8 rows (L1 broadcast)
            const float* kp = k + (size_t)bh * (TT * DK) + t * DK + k0;
            const float* qp = q + (size_t)bh * (TT * DK) + t * DK + k0;
            float4 kA = __ldg((const float4*)kp);
            float4 kB = __ldg((const float4*)(kp + 4));
            float4 qA = __ldg((const float4*)qp);
            float4 qB = __ldg((const float4*)(qp + 4));
            float kf[8] = {kA.x, kA.y, kA.z, kA.w, kB.x, kB.y, kB.z, kB.w};
            float qf[8] = {qA.x, qA.y, qA.z, qA.w, qB.x, qB.y, qB.z, qB.w};

            // one sweep over OLD state: k-dot, q-dot, k.q partials
            u64 ax = 0ull, ay = 0ull, ox = 0ull, oy = 0ull;
            float kqp = 0.0f;
#pragma unroll
            for (int kk = 0; kk < 8; kk++){
                u64 kt2 = pk1(kf[kk]);
                u64 qt2 = pk1(qf[kk]);
                ax = fma2(S[kk].x, kt2, ax);
                ay = fma2(S[kk].y, kt2, ay);
                ox = fma2(S[kk].x, qt2, ox);
                oy = fma2(S[kk].y, qt2, oy);
                kqp = fmaf(kf[kk], qf[kk], kqp);
            }
            // stage1: vector writes, lane-stride 16B -> conflict-free STS.128
            {
                float4 a, b;
                up2(ax, a.x, a.y); up2(ay, a.z, a.w);
                up2(ox, b.x, b.y); up2(oy, b.z, b.w);
                redA[buf][tid] = a;
                redB[buf][tid] = b;
                redC[buf][tid] = kqp;
            }
            __syncthreads();

            // stage2: transposed reduce -- thread (f, cg2) sums 16 row groups
            if (tid < 144){
                int f   = tid >> 4;     // 0..8
                int cg2 = tid & 15;
                float s = 0.0f;
                if (f < 4){
#pragma unroll
                    for (int r2 = 0; r2 < 16; r2++)
                        s += ((const float*)&redA[buf][r2 * 16 + cg2])[f];
                    ((float*)&sumsA[buf][cg2])[f] = s;
                } else if (f < 8){
                    int f2 = f - 4;
#pragma unroll
                    for (int r2 = 0; r2 < 16; r2++)
                        s += ((const float*)&redB[buf][r2 * 16 + cg2])[f2];
                    ((float*)&sumsB[buf][cg2])[f2] = s;
                } else {
#pragma unroll
                    for (int r2 = 0; r2 < 16; r2++)
                        s += redC[buf][r2 * 16 + cg2];
                    sumsC[buf][cg2] = s;
                }
            }
            __syncthreads();

            // stage3: vector broadcast reads, compute d' locally
            float4 sk = sumsA[buf][cg];
            float4 sq = sumsB[buf][cg];
            float  kq = sumsC[buf][cg];
            u64 sx = pk2(sk.x, sk.y), sy = pk2(sk.z, sk.w);
            u64 qx = pk2(sq.x, sq.y), qy = pk2(sq.z, sq.w);

            float4 vvf = __ldg((const float4*)(v + (size_t)(bh * TT + t) * DV + v0));
            u64 vvx = pk2(vvf.x, vvf.y);
            u64 vvy = pk2(vvf.z, vvf.w);

            float bt  = __ldg(beta + bh * TT + t);
            float bic = bt / c;
            u64 nc2  = pk1(-c);
            u64 bic2 = pk1(bic);
            u64 dx = mul2(fma2(sx, nc2, vvx), bic2);
            u64 dy = mul2(fma2(sy, nc2, vvy), bic2);

            // out_t = c * (S'_old.q + (k.q) * d')  -- one row group writes
            if (rg == 0){
                u64 kq2 = pk1(kq);
                u64 c2  = pk1(c);
                ulonglong2 o;
                o.x = mul2(fma2(kq2, dx, qx), c2);
                o.y = mul2(fma2(kq2, dy, qy), c2);
                *(ulonglong2*)(out + (size_t)(bh * TT + t) * DV + v0) = o;
            }

            // rank-1 update of S'
#pragma unroll
            for (int kk = 0; kk < 8; kk++){
                u64 kt2 = pk1(kf[kk]);
                S[kk].x = fma2(kt2, dx, S[kk].x);
                S[kk].y = fma2(kt2, dy, S[kk].y);
            }
        }

        // ---- final state writeback: state = c * S', streaming stores ----
        u64 c2 = pk1(c);
#pragma unroll
        for (int kk = 0; kk < 8; kk++){
            u64 wx = mul2(S[kk].x, c2);
            u64 wy = mul2(S[kk].y, c2);
            float4 f;
            up2(wx, f.x, f.y);
            up2(wy, f.z, f.w);
            __stcs((float4*)(sout + sbase + (size_t)(k0 + kk) * DV + v0), f);
        }
    }
}

extern "C" void kernel_launch(void* const* d_in, const int* in_sizes, int n_in,
                              void* d_out, int out_size)
{
    const float* q    = (const float*)d_in[0];
    const float* k    = (const float*)d_in[1];
    const float* v    = (const float*)d_in[2];
    const float* g    = (const float*)d_in[3];
    const float* beta = (const float*)d_in[4];
    const float* s0   = (const float*)d_in[5];
    float* out  = (float*)d_out;
    float* sout = out + (size_t)NBH * TT * DV;   // state follows the T outputs

    gdn_step_kernel<<<GRID, 256>>>(q, k, v, g, beta, s0, out, sout);
}

// round 7
// speedup vs baseline: 1.2751x; 1.2751x over previous
#include <cuda_runtime.h>
#include <cuda_bf16.h>

typedef unsigned long long u64;

#define NBH 1024   // B*H
#define TT  4
#define DK  128
#define DV  256

// ---- packed f32x2 helpers (Blackwell sm_103a) ----
__device__ __forceinline__ u64 pk2(float x, float y){
    u64 r; asm("mov.b64 %0, {%1,%2};" : "=l"(r) : "f"(x), "f"(y)); return r;
}
__device__ __forceinline__ u64 pk1(float x){ return pk2(x, x); }
__device__ __forceinline__ void up2(u64 a, float& x, float& y){
    asm("mov.b64 {%0,%1}, %2;" : "=f"(x), "=f"(y) : "l"(a));
}
__device__ __forceinline__ u64 fma2(u64 a, u64 b, u64 c){
    u64 d; asm("fma.rn.f32x2 %0, %1, %2, %3;" : "=l"(d) : "l"(a), "l"(b), "l"(c)); return d;
}
__device__ __forceinline__ u64 add2(u64 a, u64 b){
    u64 d; asm("add.rn.f32x2 %0, %1, %2;" : "=l"(d) : "l"(a), "l"(b)); return d;
}
__device__ __forceinline__ u64 mul2(u64 a, u64 b){
    u64 d; asm("mul.rn.f32x2 %0, %1, %2;" : "=l"(d) : "l"(a), "l"(b)); return d;
}
__device__ __forceinline__ u64 shflx(u64 x, int m){
    return __shfl_xor_sync(0xFFFFFFFFu, x, m);
}

// One CTA = 128 threads = one (b,h) x one EIGHTH of Dv (32 cols).
//   cg = tid & 7  -> 4 consecutive cols   (8 cgs * 4 = 32 cols)
//   rg = tid >> 3 -> 8 consecutive rows   (16 rgs * 8 = 128 rows)
// Warp = 4 row-groups x 8 cgs -> partials pre-reduced IN-WARP via two
// butterfly shuffles (xor 8, xor 16); only lanes 0-7 touch smem.
// State slice 8x4 fp32 in registers. Decay factored out (state = c*S').
// kq fusion: out = c*(S'_old.q + (k.q)*d') -> one reduction (2 barriers)/step.
__global__ __launch_bounds__(128, 8)
void gdn_step_kernel(const float* __restrict__ q, const float* __restrict__ k,
                     const float* __restrict__ v, const float* __restrict__ g,
                     const float* __restrict__ beta, const float* __restrict__ s0,
                     float* __restrict__ out, float* __restrict__ sout)
{
    const int bh    = blockIdx.x >> 3;
    const int oct   = blockIdx.x & 7;
    const int vbase = oct * 32;
    const int tid   = threadIdx.x;
    const int cg    = tid & 7;     // column group (4 cols)
    const int rg    = tid >> 3;    // row group (8 rows)
    const int wid   = tid >> 5;    // warp id (0..3)
    const int lane  = tid & 31;
    const int k0    = rg * 8;
    const int v0    = vbase + cg * 4;

    __shared__ __align__(16) float qs[TT * DK];
    __shared__ __align__(16) float ks[TT * DK];
    __shared__ __align__(16) float vs[TT * 32];
    __shared__ float gs[TT], bs[TT];
    __shared__ float4 redA[32];    // per-warp k-dot sums (4 warps x 8 cgs)
    __shared__ float4 redB[32];    // per-warp q-dot sums
    __shared__ float  redC[32];    // per-warp k.q sums
    __shared__ float4 sumsA[8];    // final per-cg sums
    __shared__ float4 sumsB[8];
    __shared__ float  sumsC[8];

    // ---- front-batched state load: 8 x LDG.128 streaming, coalesced ----
    const size_t sbase = (size_t)bh * (DK * DV);
    ulonglong2 S[8];
#pragma unroll
    for (int kk = 0; kk < 8; kk++){
        float4 f = __ldcs((const float4*)(s0 + sbase + (size_t)(k0 + kk) * DV + v0));
        S[kk].x = pk2(f.x, f.y);
        S[kk].y = pk2(f.z, f.w);
    }

    // ---- stage q/k/v/g/beta into smem ----
    {
        const int qb = bh * (TT * DK);
#pragma unroll
        for (int r = 0; r < 4; r++){
            int i = tid + r * 128;
            qs[i] = q[qb + i];
            ks[i] = k[qb + i];
        }
        {
            int t = tid >> 5, j = tid & 31;     // 128 = 4*32 exactly
            vs[tid] = v[bh * (TT * DV) + t * DV + vbase + j];
        }
        if (tid < TT){ gs[tid] = g[bh * TT + tid]; bs[tid] = beta[bh * TT + tid]; }
    }
    __syncthreads();

    float c = 1.0f;   // cumulative decay; true state = c * S'
#pragma unroll
    for (int t = 0; t < TT; t++){
        c *= __expf(gs[t]);

        // vectorized k/q fetch for this thread's 8 rows (LDS.128 broadcast)
        float4 kA = *(const float4*)&ks[t * DK + k0];
        float4 kB = *(const float4*)&ks[t * DK + k0 + 4];
        float4 qA = *(const float4*)&qs[t * DK + k0];
        float4 qB = *(const float4*)&qs[t * DK + k0 + 4];
        float kf[8] = {kA.x, kA.y, kA.z, kA.w, kB.x, kB.y, kB.z, kB.w};
        float qf[8] = {qA.x, qA.y, qA.z, qA.w, qB.x, qB.y, qB.z, qB.w};

        // one sweep over OLD state: k-dot, q-dot, k.q partials
        u64 ax = 0ull, ay = 0ull, ox = 0ull, oy = 0ull;
        float kqp = 0.0f;
#pragma unroll
        for (int kk = 0; kk < 8; kk++){
            u64 kt2 = pk1(kf[kk]);
            u64 qt2 = pk1(qf[kk]);
            ax = fma2(S[kk].x, kt2, ax);
            ay = fma2(S[kk].y, kt2, ay);
            ox = fma2(S[kk].x, qt2, ox);
            oy = fma2(S[kk].y, qt2, oy);
            kqp = fmaf(kf[kk], qf[kk], kqp);
        }

        // in-warp pre-reduction over the warp's 4 row-groups (xor 8, 16)
#pragma unroll
        for (int m = 8; m <= 16; m <<= 1){
            ax = add2(ax, shflx(ax, m));
            ay = add2(ay, shflx(ay, m));
            ox = add2(ox, shflx(ox, m));
            oy = add2(oy, shflx(oy, m));
            kqp += __shfl_xor_sync(0xFFFFFFFFu, kqp, m);
        }
        if (lane < 8){
            float4 a, b;
            up2(ax, a.x, a.y); up2(ay, a.z, a.w);
            up2(ox, b.x, b.y); up2(oy, b.z, b.w);
            redA[wid * 8 + lane] = a;
            redB[wid * 8 + lane] = b;
            redC[wid * 8 + lane] = kqp;
        }
        __syncthreads();

        // stage2: 72 threads sum the 4 warp partials per (cg, field)
        if (tid < 72){
            int f  = tid >> 3;      // 0..8
            int c2 = tid & 7;
            float s = 0.0f;
            if (f < 4){
#pragma unroll
                for (int w = 0; w < 4; w++)
                    s += ((const float*)&redA[w * 8 + c2])[f];
                ((float*)&sumsA[c2])[f] = s;
            } else if (f < 8){
                int f2 = f - 4;
#pragma unroll
                for (int w = 0; w < 4; w++)
                    s += ((const float*)&redB[w * 8 + c2])[f2];
                ((float*)&sumsB[c2])[f2] = s;
            } else {
#pragma unroll
                for (int w = 0; w < 4; w++)
                    s += redC[w * 8 + c2];
                sumsC[c2] = s;
            }
        }
        __syncthreads();

        // stage3: broadcast reads, compute d' locally
        float4 sk = sumsA[cg];
        float4 sq = sumsB[cg];
        float  kq = sumsC[cg];
        u64 sx = pk2(sk.x, sk.y), sy = pk2(sk.z, sk.w);
        u64 qx = pk2(sq.x, sq.y), qy = pk2(sq.z, sq.w);

        float4 vvf = *(const float4*)&vs[t * 32 + cg * 4];
        u64 vvx = pk2(vvf.x, vvf.y);
        u64 vvy = pk2(vvf.z, vvf.w);

        float bic = bs[t] / c;                  // beta / c
        u64 nc2  = pk1(-c);
        u64 bic2 = pk1(bic);
        u64 dx = mul2(fma2(sx, nc2, vvx), bic2);
        u64 dy = mul2(fma2(sy, nc2, vvy), bic2);

        // out_t = c * (S'_old.q + (k.q) * d')  -- row group 0 (tid<8) writes
        if (rg == 0){
            u64 kq2 = pk1(kq);
            u64 c2  = pk1(c);
            ulonglong2 o;
            o.x = mul2(fma2(kq2, dx, qx), c2);
            o.y = mul2(fma2(kq2, dy, qy), c2);
            *(ulonglong2*)(out + (size_t)(bh * TT + t) * DV + v0) = o;
        }

        // rank-1 update of S'
#pragma unroll
        for (int kk = 0; kk < 8; kk++){
            u64 kt2 = pk1(kf[kk]);
            S[kk].x = fma2(kt2, dx, S[kk].x);
            S[kk].y = fma2(kt2, dy, S[kk].y);
        }
    }

    // ---- final state writeback: state = c * S', streaming stores ----
    u64 c2 = pk1(c);
#pragma unroll
    for (int kk = 0; kk < 8; kk++){
        u64 wx = mul2(S[kk].x, c2);
        u64 wy = mul2(S[kk].y, c2);
        float4 f;
        up2(wx, f.x, f.y);
        up2(wy, f.z, f.w);
        __stcs((float4*)(sout + sbase + (size_t)(k0 + kk) * DV + v0), f);
    }
}

extern "C" void kernel_launch(void* const* d_in, const int* in_sizes, int n_in,
                              void* d_out, int out_size)
{
    const float* q    = (const float*)d_in[0];
    const float* k    = (const float*)d_in[1];
    const float* v    = (const float*)d_in[2];
    const float* g    = (const float*)d_in[3];
    const float* beta = (const float*)d_in[4];
    const float* s0   = (const float*)d_in[5];
    float* out  = (float*)d_out;
    float* sout = out + (size_t)NBH * TT * DV;   // state follows the T outputs

    gdn_step_kernel<<<NBH * 8, 128>>>(q, k, v, g, beta, s0, out, sout);
}